// round 2
// baseline (speedup 1.0000x reference)
#include <cuda_runtime.h>
#include <cstdint>

// ---------------------------------------------------------------------------
// PMWA_24842090840472: 3-hop gated graph aggregation
//   h0 = l2norm(x)
//   for k in 0..2:
//     e_j   = <h[src_j], h[dst_j]>          (per edge)
//     a_j   = sigmoid(e_j)
//     aggr  = segment_sum(a_j * h[src_j], dst)
//     h     = l2norm(aggr + 0.1 * normal(jax threefry, partitionable))
//   out = stack([h0,h1,h2,h3])   [4, N, 128] f32
//
// NOTE: edge_index is int32 on device (JAX x64-disabled downcasts int64).
// ---------------------------------------------------------------------------

#define DIMS 128
#define NMAX 65537
#define EMAX 1100000

__device__ int g_count[NMAX];
__device__ int g_start[NMAX];
__device__ int g_cursor[NMAX];
__device__ int g_csr[EMAX];

// ---------------- Threefry-2x32 (JAX key schedule) -------------------------
#define TF_ROUND(x0, x1, r) \
    do { x0 += x1; x1 = ((x1) << (r)) | ((x1) >> (32 - (r))); x1 ^= x0; } while (0)

__host__ __device__ inline void tf2x32(uint32_t k0, uint32_t k1,
                                       uint32_t x0, uint32_t x1,
                                       uint32_t& o0, uint32_t& o1) {
    uint32_t ks0 = k0, ks1 = k1, ks2 = 0x1BD11BDAu ^ k0 ^ k1;
    x0 += ks0; x1 += ks1;
    TF_ROUND(x0, x1, 13); TF_ROUND(x0, x1, 15); TF_ROUND(x0, x1, 26); TF_ROUND(x0, x1, 6);
    x0 += ks1; x1 += ks2 + 1u;
    TF_ROUND(x0, x1, 17); TF_ROUND(x0, x1, 29); TF_ROUND(x0, x1, 16); TF_ROUND(x0, x1, 24);
    x0 += ks2; x1 += ks0 + 2u;
    TF_ROUND(x0, x1, 13); TF_ROUND(x0, x1, 15); TF_ROUND(x0, x1, 26); TF_ROUND(x0, x1, 6);
    x0 += ks0; x1 += ks1 + 3u;
    TF_ROUND(x0, x1, 17); TF_ROUND(x0, x1, 29); TF_ROUND(x0, x1, 16); TF_ROUND(x0, x1, 24);
    x0 += ks1; x1 += ks2 + 4u;
    TF_ROUND(x0, x1, 13); TF_ROUND(x0, x1, 15); TF_ROUND(x0, x1, 26); TF_ROUND(x0, x1, 6);
    x0 += ks2; x1 += ks0 + 5u;
    o0 = x0; o1 = x1;
}

// XLA/Giles float32 erfinv polynomial
__device__ inline float erfinv_xla(float x) {
    float w = -__logf(fmaf(-x, x, 1.0f));
    float p;
    if (w < 5.0f) {
        w -= 2.5f;
        p = 2.81022636e-08f;
        p = fmaf(p, w, 3.43273939e-07f);
        p = fmaf(p, w, -3.5233877e-06f);
        p = fmaf(p, w, -4.39150654e-06f);
        p = fmaf(p, w, 0.00021858087f);
        p = fmaf(p, w, -0.00125372503f);
        p = fmaf(p, w, -0.00417768164f);
        p = fmaf(p, w, 0.246640727f);
        p = fmaf(p, w, 1.50140941f);
    } else {
        w = sqrtf(w) - 3.0f;
        p = -0.000200214257f;
        p = fmaf(p, w, 0.000100950558f);
        p = fmaf(p, w, 0.00134934322f);
        p = fmaf(p, w, -0.00367342844f);
        p = fmaf(p, w, 0.00573950773f);
        p = fmaf(p, w, -0.0076224613f);
        p = fmaf(p, w, 0.00943887047f);
        p = fmaf(p, w, 1.00167406f);
        p = fmaf(p, w, 2.83297682f);
    }
    return p * x;
}

// jax.random.normal, threefry partitionable path, element index < 2^32
__device__ inline float tf_normal(uint32_t k0, uint32_t k1, uint32_t idx) {
    uint32_t o0, o1;
    tf2x32(k0, k1, 0u, idx, o0, o1);
    uint32_t bits = o0 ^ o1;                                  // 32-bit fold
    float f = __uint_as_float(0x3f800000u | (bits >> 9)) - 1.0f;  // [0,1)
    float u = fmaf(f, 2.0f, -0.99999994f);                    // [-1+eps, 1)
    return 1.41421354f * erfinv_xla(u);                       // sqrt(2)*erfinv
}

// ---------------- CSR build ------------------------------------------------
__global__ void k_zero(int N) {
    int i = blockIdx.x * blockDim.x + threadIdx.x;
    if (i < N) g_count[i] = 0;
}

__global__ void k_hist(const int* __restrict__ ei, int E) {
    int e = blockIdx.x * blockDim.x + threadIdx.x;
    if (e < E) atomicAdd(&g_count[ei[E + e]], 1);
}

__global__ void k_scan(int N, int E) {
    __shared__ int s[1024];
    int tid = threadIdx.x;
    int chunk = (N + 1023) >> 10;
    int lo = tid * chunk;
    int hi = min(lo + chunk, N);
    int sum = 0;
    for (int i = lo; i < hi; i++) sum += g_count[i];
    s[tid] = sum;
    __syncthreads();
    for (int off = 1; off < 1024; off <<= 1) {
        int v = (tid >= off) ? s[tid - off] : 0;
        __syncthreads();
        s[tid] += v;
        __syncthreads();
    }
    int run = (tid > 0) ? s[tid - 1] : 0;
    for (int i = lo; i < hi; i++) {
        g_start[i] = run;
        g_cursor[i] = run;
        run += g_count[i];
    }
    if (tid == 0) g_start[N] = E;
}

__global__ void k_fill(const int* __restrict__ ei, int E) {
    int e = blockIdx.x * blockDim.x + threadIdx.x;
    if (e < E) {
        int d = ei[E + e];
        int p = atomicAdd(&g_cursor[d], 1);
        g_csr[p] = ei[e];
    }
}

// ---------------- normalize x -> out[0] ------------------------------------
__global__ void k_norm(const float* __restrict__ src, float* __restrict__ dst, int N) {
    int warp = (blockIdx.x * blockDim.x + threadIdx.x) >> 5;
    int lane = threadIdx.x & 31;
    if (warp >= N) return;
    const float4* sv = (const float4*)src;
    float4 a = sv[(size_t)warp * 32 + lane];
    float ss = fmaf(a.x, a.x, fmaf(a.y, a.y, fmaf(a.z, a.z, a.w * a.w)));
    ss += __shfl_xor_sync(0xffffffffu, ss, 16);
    ss += __shfl_xor_sync(0xffffffffu, ss, 8);
    ss += __shfl_xor_sync(0xffffffffu, ss, 4);
    ss += __shfl_xor_sync(0xffffffffu, ss, 2);
    ss += __shfl_xor_sync(0xffffffffu, ss, 1);
    float inv = 1.0f / fmaxf(sqrtf(ss), 1e-12f);
    a.x *= inv; a.y *= inv; a.z *= inv; a.w *= inv;
    ((float4*)dst)[(size_t)warp * 32 + lane] = a;
}

// ---------------- per-hop aggregate (warp per dst node) --------------------
__global__ void k_aggr(const float* __restrict__ h, float* __restrict__ out, int N) {
    int warp = (blockIdx.x * blockDim.x + threadIdx.x) >> 5;
    int lane = threadIdx.x & 31;
    if (warp >= N) return;
    const float4* hv = (const float4*)h;
    float4 hd = hv[(size_t)warp * 32 + lane];
    float4 acc = make_float4(0.f, 0.f, 0.f, 0.f);
    int e = g_start[warp];
    int end = g_start[warp + 1];
    if (e < end) {
        int s = g_csr[e];
        float4 v = __ldg(&hv[(size_t)s * 32 + lane]);
        while (++e < end) {
            int s2 = g_csr[e];                                   // prefetch next
            float4 v2 = __ldg(&hv[(size_t)s2 * 32 + lane]);
            float d = fmaf(v.x, hd.x, fmaf(v.y, hd.y, fmaf(v.z, hd.z, v.w * hd.w)));
            d += __shfl_xor_sync(0xffffffffu, d, 16);
            d += __shfl_xor_sync(0xffffffffu, d, 8);
            d += __shfl_xor_sync(0xffffffffu, d, 4);
            d += __shfl_xor_sync(0xffffffffu, d, 2);
            d += __shfl_xor_sync(0xffffffffu, d, 1);
            float alpha = 1.0f / (1.0f + __expf(-d));
            acc.x = fmaf(alpha, v.x, acc.x);
            acc.y = fmaf(alpha, v.y, acc.y);
            acc.z = fmaf(alpha, v.z, acc.z);
            acc.w = fmaf(alpha, v.w, acc.w);
            v = v2;
        }
        float d = fmaf(v.x, hd.x, fmaf(v.y, hd.y, fmaf(v.z, hd.z, v.w * hd.w)));
        d += __shfl_xor_sync(0xffffffffu, d, 16);
        d += __shfl_xor_sync(0xffffffffu, d, 8);
        d += __shfl_xor_sync(0xffffffffu, d, 4);
        d += __shfl_xor_sync(0xffffffffu, d, 2);
        d += __shfl_xor_sync(0xffffffffu, d, 1);
        float alpha = 1.0f / (1.0f + __expf(-d));
        acc.x = fmaf(alpha, v.x, acc.x);
        acc.y = fmaf(alpha, v.y, acc.y);
        acc.z = fmaf(alpha, v.z, acc.z);
        acc.w = fmaf(alpha, v.w, acc.w);
    }
    ((float4*)out)[(size_t)warp * 32 + lane] = acc;
}

// ---------------- fused noise-add + l2-normalize (in place) ----------------
__global__ void k_noise_norm(float* __restrict__ buf, int N, uint32_t k0, uint32_t k1) {
    int warp = (blockIdx.x * blockDim.x + threadIdx.x) >> 5;
    int lane = threadIdx.x & 31;
    if (warp >= N) return;
    float4* p = (float4*)buf + (size_t)warp * 32 + lane;
    float4 a = *p;
    uint32_t base = (uint32_t)warp * 128u + (uint32_t)lane * 4u;
    a.x = fmaf(0.1f, tf_normal(k0, k1, base + 0u), a.x);
    a.y = fmaf(0.1f, tf_normal(k0, k1, base + 1u), a.y);
    a.z = fmaf(0.1f, tf_normal(k0, k1, base + 2u), a.z);
    a.w = fmaf(0.1f, tf_normal(k0, k1, base + 3u), a.w);
    float ss = fmaf(a.x, a.x, fmaf(a.y, a.y, fmaf(a.z, a.z, a.w * a.w)));
    ss += __shfl_xor_sync(0xffffffffu, ss, 16);
    ss += __shfl_xor_sync(0xffffffffu, ss, 8);
    ss += __shfl_xor_sync(0xffffffffu, ss, 4);
    ss += __shfl_xor_sync(0xffffffffu, ss, 2);
    ss += __shfl_xor_sync(0xffffffffu, ss, 1);
    float inv = 1.0f / fmaxf(sqrtf(ss), 1e-12f);
    a.x *= inv; a.y *= inv; a.z *= inv; a.w *= inv;
    *p = a;
}

// ---------------------------------------------------------------------------
extern "C" void kernel_launch(void* const* d_in, const int* in_sizes, int n_in,
                              void* d_out, int out_size) {
    const float* x = (const float*)d_in[0];
    const int* ei = (const int*)d_in[1];      // int32! (JAX x64 disabled)
    int N = in_sizes[0] / DIMS;
    int E = in_sizes[1] / 2;
    float* out = (float*)d_out;
    size_t ND = (size_t)N * DIMS;

    // Host-side hop keys: noise_keys = split(key(1)=(0,1), 3), foldlike
    // (partitionable): subkey_i = threefry2x32((0,1), (0, i))
    uint32_t hk[3][2];
    for (uint32_t i = 0; i < 3; i++) {
        tf2x32(0u, 1u, 0u, i, hk[i][0], hk[i][1]);
    }

    int tEdges = (E + 255) / 256;
    int tNodes = (N + 255) / 256;
    int wNodes = (N + 7) / 8;   // 8 warps per 256-thread block

    // Build CSR (dst -> edge list of src)
    k_zero<<<tNodes, 256>>>(N);
    k_hist<<<tEdges, 256>>>(ei, E);
    k_scan<<<1, 1024>>>(N, E);
    k_fill<<<tEdges, 256>>>(ei, E);

    // out[0] = normalize(x)
    k_norm<<<wNodes, 256>>>(x, out, N);

    // 3 hops
    for (int k = 0; k < 3; k++) {
        const float* h = out + (size_t)k * ND;
        float* nxt = out + (size_t)(k + 1) * ND;
        k_aggr<<<wNodes, 256>>>(h, nxt, N);
        k_noise_norm<<<wNodes, 256>>>(nxt, N, hk[k][0], hk[k][1]);
    }
}

// round 3
// speedup vs baseline: 1.1428x; 1.1428x over previous
#include <cuda_runtime.h>
#include <cstdint>

// ---------------------------------------------------------------------------
// PMWA_24842090840472: 3-hop gated graph aggregation
//   h0 = l2norm(x)
//   for k in 0..2:
//     e_j   = <h[src_j], h[dst_j]>   ;  a_j = sigmoid(e_j)
//     aggr  = segment_sum(a_j * h[src_j], dst)
//     h     = l2norm(aggr + 0.1 * normal(jax threefry, partitionable))
//   out = stack([h0,h1,h2,h3])   [4, N, 128] f32
//
// R3: fused noise+normalize into the aggregate kernel (warp-local aggr rows),
//     4-edge ILP batching to pipeline the shfl-reduce chains.
// ---------------------------------------------------------------------------

#define DIMS 128
#define NMAX 65537
#define EMAX 1100000

__device__ int g_count[NMAX];
__device__ int g_start[NMAX];
__device__ int g_cursor[NMAX];
__device__ int g_csr[EMAX];

// ---------------- Threefry-2x32 (JAX key schedule) -------------------------
#define TF_ROUND(x0, x1, r) \
    do { x0 += x1; x1 = ((x1) << (r)) | ((x1) >> (32 - (r))); x1 ^= x0; } while (0)

__host__ __device__ inline void tf2x32(uint32_t k0, uint32_t k1,
                                       uint32_t x0, uint32_t x1,
                                       uint32_t& o0, uint32_t& o1) {
    uint32_t ks0 = k0, ks1 = k1, ks2 = 0x1BD11BDAu ^ k0 ^ k1;
    x0 += ks0; x1 += ks1;
    TF_ROUND(x0, x1, 13); TF_ROUND(x0, x1, 15); TF_ROUND(x0, x1, 26); TF_ROUND(x0, x1, 6);
    x0 += ks1; x1 += ks2 + 1u;
    TF_ROUND(x0, x1, 17); TF_ROUND(x0, x1, 29); TF_ROUND(x0, x1, 16); TF_ROUND(x0, x1, 24);
    x0 += ks2; x1 += ks0 + 2u;
    TF_ROUND(x0, x1, 13); TF_ROUND(x0, x1, 15); TF_ROUND(x0, x1, 26); TF_ROUND(x0, x1, 6);
    x0 += ks0; x1 += ks1 + 3u;
    TF_ROUND(x0, x1, 17); TF_ROUND(x0, x1, 29); TF_ROUND(x0, x1, 16); TF_ROUND(x0, x1, 24);
    x0 += ks1; x1 += ks2 + 4u;
    TF_ROUND(x0, x1, 13); TF_ROUND(x0, x1, 15); TF_ROUND(x0, x1, 26); TF_ROUND(x0, x1, 6);
    x0 += ks2; x1 += ks0 + 5u;
    o0 = x0; o1 = x1;
}

// XLA/Giles float32 erfinv polynomial
__device__ inline float erfinv_xla(float x) {
    float w = -__logf(fmaf(-x, x, 1.0f));
    float p;
    if (w < 5.0f) {
        w -= 2.5f;
        p = 2.81022636e-08f;
        p = fmaf(p, w, 3.43273939e-07f);
        p = fmaf(p, w, -3.5233877e-06f);
        p = fmaf(p, w, -4.39150654e-06f);
        p = fmaf(p, w, 0.00021858087f);
        p = fmaf(p, w, -0.00125372503f);
        p = fmaf(p, w, -0.00417768164f);
        p = fmaf(p, w, 0.246640727f);
        p = fmaf(p, w, 1.50140941f);
    } else {
        w = sqrtf(w) - 3.0f;
        p = -0.000200214257f;
        p = fmaf(p, w, 0.000100950558f);
        p = fmaf(p, w, 0.00134934322f);
        p = fmaf(p, w, -0.00367342844f);
        p = fmaf(p, w, 0.00573950773f);
        p = fmaf(p, w, -0.0076224613f);
        p = fmaf(p, w, 0.00943887047f);
        p = fmaf(p, w, 1.00167406f);
        p = fmaf(p, w, 2.83297682f);
    }
    return p * x;
}

// jax.random.normal, threefry partitionable path, element index < 2^32
__device__ inline float tf_normal(uint32_t k0, uint32_t k1, uint32_t idx) {
    uint32_t o0, o1;
    tf2x32(k0, k1, 0u, idx, o0, o1);
    uint32_t bits = o0 ^ o1;                                  // 32-bit fold
    float f = __uint_as_float(0x3f800000u | (bits >> 9)) - 1.0f;  // [0,1)
    float u = fmaf(f, 2.0f, -0.99999994f);                    // [-1+eps, 1)
    return 1.41421354f * erfinv_xla(u);                       // sqrt(2)*erfinv
}

// ---------------- CSR build ------------------------------------------------
__global__ void k_zero(int N) {
    int i = blockIdx.x * blockDim.x + threadIdx.x;
    if (i < N) g_count[i] = 0;
}

__global__ void k_hist(const int* __restrict__ ei, int E) {
    int e = blockIdx.x * blockDim.x + threadIdx.x;
    if (e < E) atomicAdd(&g_count[ei[E + e]], 1);
}

__global__ void k_scan(int N, int E) {
    __shared__ int s[1024];
    int tid = threadIdx.x;
    int chunk = (N + 1023) >> 10;
    int lo = tid * chunk;
    int hi = min(lo + chunk, N);
    int sum = 0;
    for (int i = lo; i < hi; i++) sum += g_count[i];
    s[tid] = sum;
    __syncthreads();
    for (int off = 1; off < 1024; off <<= 1) {
        int v = (tid >= off) ? s[tid - off] : 0;
        __syncthreads();
        s[tid] += v;
        __syncthreads();
    }
    int run = (tid > 0) ? s[tid - 1] : 0;
    for (int i = lo; i < hi; i++) {
        g_start[i] = run;
        g_cursor[i] = run;
        run += g_count[i];
    }
    if (tid == 0) g_start[N] = E;
}

__global__ void k_fill(const int* __restrict__ ei, int E) {
    int e = blockIdx.x * blockDim.x + threadIdx.x;
    if (e < E) {
        int d = ei[E + e];
        int p = atomicAdd(&g_cursor[d], 1);
        g_csr[p] = ei[e];
    }
}

// ---------------- helpers --------------------------------------------------
__device__ __forceinline__ float warp_dot4(const float4& v, const float4& hd) {
    return fmaf(v.x, hd.x, fmaf(v.y, hd.y, fmaf(v.z, hd.z, v.w * hd.w)));
}

#define BFLY(d)                                         \
    d += __shfl_xor_sync(0xffffffffu, d, 16);           \
    d += __shfl_xor_sync(0xffffffffu, d, 8);            \
    d += __shfl_xor_sync(0xffffffffu, d, 4);            \
    d += __shfl_xor_sync(0xffffffffu, d, 2);            \
    d += __shfl_xor_sync(0xffffffffu, d, 1);

__device__ __forceinline__ float sigm(float d) {
    return 1.0f / (1.0f + __expf(-d));
}

// ---------------- normalize x -> out[0] ------------------------------------
__global__ void k_norm(const float* __restrict__ src, float* __restrict__ dst, int N) {
    int warp = (blockIdx.x * blockDim.x + threadIdx.x) >> 5;
    int lane = threadIdx.x & 31;
    if (warp >= N) return;
    const float4* sv = (const float4*)src;
    float4 a = sv[(size_t)warp * 32 + lane];
    float ss = warp_dot4(a, a);
    BFLY(ss);
    float inv = 1.0f / fmaxf(sqrtf(ss), 1e-12f);
    a.x *= inv; a.y *= inv; a.z *= inv; a.w *= inv;
    ((float4*)dst)[(size_t)warp * 32 + lane] = a;
}

// ---- fused hop: aggregate + noise + normalize (warp per dst node) ----------
__global__ void k_hop(const float* __restrict__ h, float* __restrict__ out, int N,
                      uint32_t nk0, uint32_t nk1) {
    int warp = (blockIdx.x * blockDim.x + threadIdx.x) >> 5;
    int lane = threadIdx.x & 31;
    if (warp >= N) return;
    const float4* hv = (const float4*)h;
    float4 hd = hv[(size_t)warp * 32 + lane];
    float4 acc = make_float4(0.f, 0.f, 0.f, 0.f);
    int e = g_start[warp];
    int end = g_start[warp + 1];

    // 4-edge batches: independent dot/shfl-reduce chains pipeline in the SMSP
    for (; e + 4 <= end; e += 4) {
        int s0 = g_csr[e], s1 = g_csr[e + 1], s2 = g_csr[e + 2], s3 = g_csr[e + 3];
        float4 v0 = __ldg(&hv[(size_t)s0 * 32 + lane]);
        float4 v1 = __ldg(&hv[(size_t)s1 * 32 + lane]);
        float4 v2 = __ldg(&hv[(size_t)s2 * 32 + lane]);
        float4 v3 = __ldg(&hv[(size_t)s3 * 32 + lane]);
        float d0 = warp_dot4(v0, hd);
        float d1 = warp_dot4(v1, hd);
        float d2 = warp_dot4(v2, hd);
        float d3 = warp_dot4(v3, hd);
        #pragma unroll
        for (int off = 16; off >= 1; off >>= 1) {
            d0 += __shfl_xor_sync(0xffffffffu, d0, off);
            d1 += __shfl_xor_sync(0xffffffffu, d1, off);
            d2 += __shfl_xor_sync(0xffffffffu, d2, off);
            d3 += __shfl_xor_sync(0xffffffffu, d3, off);
        }
        float a0 = sigm(d0), a1 = sigm(d1), a2 = sigm(d2), a3 = sigm(d3);
        acc.x = fmaf(a0, v0.x, fmaf(a1, v1.x, fmaf(a2, v2.x, fmaf(a3, v3.x, acc.x))));
        acc.y = fmaf(a0, v0.y, fmaf(a1, v1.y, fmaf(a2, v2.y, fmaf(a3, v3.y, acc.y))));
        acc.z = fmaf(a0, v0.z, fmaf(a1, v1.z, fmaf(a2, v2.z, fmaf(a3, v3.z, acc.z))));
        acc.w = fmaf(a0, v0.w, fmaf(a1, v1.w, fmaf(a2, v2.w, fmaf(a3, v3.w, acc.w))));
    }
    // remainder
    for (; e < end; e++) {
        int s = g_csr[e];
        float4 v = __ldg(&hv[(size_t)s * 32 + lane]);
        float d = warp_dot4(v, hd);
        BFLY(d);
        float a = sigm(d);
        acc.x = fmaf(a, v.x, acc.x);
        acc.y = fmaf(a, v.y, acc.y);
        acc.z = fmaf(a, v.z, acc.z);
        acc.w = fmaf(a, v.w, acc.w);
    }

    // fused: + SIGMA*normal, then l2-normalize, store final row
    uint32_t base = (uint32_t)warp * 128u + (uint32_t)lane * 4u;
    acc.x = fmaf(0.1f, tf_normal(nk0, nk1, base + 0u), acc.x);
    acc.y = fmaf(0.1f, tf_normal(nk0, nk1, base + 1u), acc.y);
    acc.z = fmaf(0.1f, tf_normal(nk0, nk1, base + 2u), acc.z);
    acc.w = fmaf(0.1f, tf_normal(nk0, nk1, base + 3u), acc.w);
    float ss = warp_dot4(acc, acc);
    BFLY(ss);
    float inv = 1.0f / fmaxf(sqrtf(ss), 1e-12f);
    acc.x *= inv; acc.y *= inv; acc.z *= inv; acc.w *= inv;
    ((float4*)out)[(size_t)warp * 32 + lane] = acc;
}

// ---------------------------------------------------------------------------
extern "C" void kernel_launch(void* const* d_in, const int* in_sizes, int n_in,
                              void* d_out, int out_size) {
    const float* x = (const float*)d_in[0];
    const int* ei = (const int*)d_in[1];      // int32 (JAX x64 disabled)
    int N = in_sizes[0] / DIMS;
    int E = in_sizes[1] / 2;
    float* out = (float*)d_out;
    size_t ND = (size_t)N * DIMS;

    // Host-side hop keys: split(key(1)=(0,1), 3), foldlike (partitionable)
    uint32_t hk[3][2];
    for (uint32_t i = 0; i < 3; i++) {
        tf2x32(0u, 1u, 0u, i, hk[i][0], hk[i][1]);
    }

    int tEdges = (E + 255) / 256;
    int tNodes = (N + 255) / 256;
    int wNodes = (N + 7) / 8;   // 8 warps per 256-thread block

    // Build CSR (dst -> edge list of src)
    k_zero<<<tNodes, 256>>>(N);
    k_hist<<<tEdges, 256>>>(ei, E);
    k_scan<<<1, 1024>>>(N, E);
    k_fill<<<tEdges, 256>>>(ei, E);

    // out[0] = normalize(x)
    k_norm<<<wNodes, 256>>>(x, out, N);

    // 3 fused hops
    for (int k = 0; k < 3; k++) {
        const float* h = out + (size_t)k * ND;
        float* nxt = out + (size_t)(k + 1) * ND;
        k_hop<<<wNodes, 256>>>(h, nxt, N, hk[k][0], hk[k][1]);
    }
}